// round 8
// baseline (speedup 1.0000x reference)
#include <cuda_runtime.h>
#include <cuda_bf16.h>

// Two-kernel split.
// K1 (gather, barrier-free): spart[h][row][f] = sum_{j in half h} adj*feat,
//                            degp[h][row]    = sum_{j in half h} adj
// K2 (epilogue GEMM): out[row,o] = relu( sum_f (sp0+sp1)[row,f]*W[f,o]
//                                        + bias[o]*(dg0+dg1)[row] )

#define MJ   128
#define FE   64
#define FC   128
#define NROW 2048

__device__ float g_spart[2][NROW][FC];   // 2 MB scratch (allowed: static device)
__device__ float g_degp[2][NROW];

// ---------------------------------------------------------------------------
// Kernel 1: pure gather. 256 thr = 8 warps = 4 rows/block, 2 warps per row.
// Each warp: 64-wide j-half -> in-warp compaction (zero-padded to full 8-deep
// batches) -> gather with 8 LDG.128 in flight -> write partial s to scratch.
// NO __syncthreads anywhere: warps never wait on each other.
// ---------------------------------------------------------------------------
__global__ __launch_bounds__(256, 4)
void gcn_gather_kernel(const float* __restrict__ sf1,
                       const float* __restrict__ sf2,
                       const float* __restrict__ adj)
{
    __shared__ int   s_off[8][72];
    __shared__ float s_val[8][72];

    const int t    = threadIdx.x;
    const int w    = t >> 5;
    const int lane = t & 31;
    const int pr   = w >> 1;               // row within block
    const int h    = w & 1;                // j-half
    const int row  = blockIdx.x * 4 + pr;

    // adj half -> compact (warp-local)
    const float* arow = adj + (size_t)row * MJ + h * 64;
    const float a0 = __ldg(arow + lane);
    const float a1 = __ldg(arow + lane + 32);
    const unsigned b0 = __ballot_sync(0xffffffffu, a0 != 0.0f);
    const unsigned b1 = __ballot_sync(0xffffffffu, a1 != 0.0f);
    const int c0  = __popc(b0);
    const int nnz = c0 + __popc(b1);
    const unsigned lm = (1u << lane) - 1u;
    if (a0 != 0.0f) { const int p = __popc(b0 & lm);
                      s_off[w][p] = (h * 64 + lane     ) * FE; s_val[w][p] = a0; }
    if (a1 != 0.0f) { const int p = c0 + __popc(b1 & lm);
                      s_off[w][p] = (h * 64 + lane + 32) * FE; s_val[w][p] = a1; }
    if (lane < 8) {                        // pad: batches always full
        s_off[w][nnz + lane] = 0;
        s_val[w][nnz + lane] = 0.0f;
    }
    {
        float d = a0 + a1;
        #pragma unroll
        for (int off = 16; off > 0; off >>= 1)
            d += __shfl_down_sync(0xffffffffu, d, off);
        if (lane == 0) g_degp[h][row] = d;
    }
    __syncwarp();

    // gather: lanes 0-15 sf1 (ch 0..63), lanes 16-31 sf2 (ch 64..127)
    const float* base = ((lane < 16) ? sf1 : sf2)
                      + (size_t)row * MJ * FE + (lane & 15) * 4;
    float4 acc0 = make_float4(0.f, 0.f, 0.f, 0.f);
    float4 acc1 = make_float4(0.f, 0.f, 0.f, 0.f);
    for (int k = 0; k < nnz; k += 8) {
        const int o0 = s_off[w][k    ], o1 = s_off[w][k + 1];
        const int o2 = s_off[w][k + 2], o3 = s_off[w][k + 3];
        const int o4 = s_off[w][k + 4], o5 = s_off[w][k + 5];
        const int o6 = s_off[w][k + 6], o7 = s_off[w][k + 7];
        const float4 v0 = __ldcs(reinterpret_cast<const float4*>(base + o0));
        const float4 v1 = __ldcs(reinterpret_cast<const float4*>(base + o1));
        const float4 v2 = __ldcs(reinterpret_cast<const float4*>(base + o2));
        const float4 v3 = __ldcs(reinterpret_cast<const float4*>(base + o3));
        const float4 v4 = __ldcs(reinterpret_cast<const float4*>(base + o4));
        const float4 v5 = __ldcs(reinterpret_cast<const float4*>(base + o5));
        const float4 v6 = __ldcs(reinterpret_cast<const float4*>(base + o6));
        const float4 v7 = __ldcs(reinterpret_cast<const float4*>(base + o7));
        const float q0 = s_val[w][k    ], q1 = s_val[w][k + 1];
        const float q2 = s_val[w][k + 2], q3 = s_val[w][k + 3];
        const float q4 = s_val[w][k + 4], q5 = s_val[w][k + 5];
        const float q6 = s_val[w][k + 6], q7 = s_val[w][k + 7];
        acc0.x += q0 * v0.x; acc0.y += q0 * v0.y; acc0.z += q0 * v0.z; acc0.w += q0 * v0.w;
        acc1.x += q1 * v1.x; acc1.y += q1 * v1.y; acc1.z += q1 * v1.z; acc1.w += q1 * v1.w;
        acc0.x += q2 * v2.x; acc0.y += q2 * v2.y; acc0.z += q2 * v2.z; acc0.w += q2 * v2.w;
        acc1.x += q3 * v3.x; acc1.y += q3 * v3.y; acc1.z += q3 * v3.z; acc1.w += q3 * v3.w;
        acc0.x += q4 * v4.x; acc0.y += q4 * v4.y; acc0.z += q4 * v4.z; acc0.w += q4 * v4.w;
        acc1.x += q5 * v5.x; acc1.y += q5 * v5.y; acc1.z += q5 * v5.z; acc1.w += q5 * v5.w;
        acc0.x += q6 * v6.x; acc0.y += q6 * v6.y; acc0.z += q6 * v6.z; acc0.w += q6 * v6.w;
        acc1.x += q7 * v7.x; acc1.y += q7 * v7.y; acc1.z += q7 * v7.z; acc1.w += q7 * v7.w;
    }
    float4 s4;
    s4.x = acc0.x + acc1.x; s4.y = acc0.y + acc1.y;
    s4.z = acc0.z + acc1.z; s4.w = acc0.w + acc1.w;
    reinterpret_cast<float4*>(g_spart[h][row])[lane] = s4;
}

// ---------------------------------------------------------------------------
// Kernel 2: epilogue GEMM. 8 rows/block, grid 256 x 256 thr.
// Warp w owns f-slice [w*16, w*16+16); each W float4 read serves 8 rows.
// ---------------------------------------------------------------------------
__global__ __launch_bounds__(256, 4)
void gcn_gemm_kernel(const float* __restrict__ W,
                     const float* __restrict__ bias,
                     float* __restrict__ out)
{
    __shared__ float  s_sm[8][FC];
    __shared__ float  s_deg[8];
    __shared__ float4 red4[8][8][32];

    const int t    = threadIdx.x;
    const int w    = t >> 5;
    const int lane = t & 31;
    const int row0 = blockIdx.x * 8;

    // load + combine partial s vectors (8 rows x 32 quads = 256 threads)
    {
        const int r = t >> 5, q = t & 31;
        const float4 p0 = reinterpret_cast<const float4*>(g_spart[0][row0 + r])[q];
        const float4 p1 = reinterpret_cast<const float4*>(g_spart[1][row0 + r])[q];
        float4 s;
        s.x = p0.x + p1.x; s.y = p0.y + p1.y;
        s.z = p0.z + p1.z; s.w = p0.w + p1.w;
        reinterpret_cast<float4*>(s_sm[r])[q] = s;
        if (q == 0) s_deg[r] = g_degp[0][row0 + r] + g_degp[1][row0 + r];
    }
    __syncthreads();

    // GEMM: 8-row register blocking, 8-way split-K
    float4 acc[8];
    #pragma unroll
    for (int r = 0; r < 8; ++r) acc[r] = make_float4(0.f, 0.f, 0.f, 0.f);
    {
        const int f0 = w * 16;
        const float4* W4 = reinterpret_cast<const float4*>(W);
        #pragma unroll
        for (int kk = 0; kk < 16; ++kk) {
            const int f = f0 + kk;
            const float4 wv = W4[f * 32 + lane];   // L1/L2-resident, coalesced
            #pragma unroll
            for (int r = 0; r < 8; ++r) {
                const float s = s_sm[r][f];        // broadcast LDS
                acc[r].x += s * wv.x; acc[r].y += s * wv.y;
                acc[r].z += s * wv.z; acc[r].w += s * wv.w;
            }
        }
        #pragma unroll
        for (int r = 0; r < 8; ++r) red4[w][r][lane] = acc[r];
    }
    __syncthreads();

    // combine 8 f-slices + bias*deg + relu + store
    {
        const int r = t >> 5, q = t & 31;
        float4 rs = red4[0][r][q];
        #pragma unroll
        for (int sl = 1; sl < 8; ++sl) {
            const float4 p = red4[sl][r][q];
            rs.x += p.x; rs.y += p.y; rs.z += p.z; rs.w += p.w;
        }
        const float4 bb = reinterpret_cast<const float4*>(bias)[q];
        const float  d  = s_deg[r];
        float4 o4;
        o4.x = fmaxf(rs.x + bb.x * d, 0.0f);
        o4.y = fmaxf(rs.y + bb.y * d, 0.0f);
        o4.z = fmaxf(rs.z + bb.z * d, 0.0f);
        o4.w = fmaxf(rs.w + bb.w * d, 0.0f);
        reinterpret_cast<float4*>(out)[(size_t)(row0 + r) * 32 + q] = o4;
    }
}

extern "C" void kernel_launch(void* const* d_in, const int* in_sizes, int n_in,
                              void* d_out, int out_size)
{
    const float* sf1  = (const float*)d_in[0];  // (16,128,128,64)
    const float* sf2  = (const float*)d_in[1];  // (16,128,128,64)
    const float* adj  = (const float*)d_in[2];  // (16,128,128)
    const float* W    = (const float*)d_in[3];  // (128,128)
    const float* bias = (const float*)d_in[4];  // (128,)
    float* out = (float*)d_out;                 // (16,128,128)

    gcn_gather_kernel<<<NROW / 4, 256>>>(sf1, sf2, adj);
    gcn_gemm_kernel<<<NROW / 8, 256>>>(W, bias, out);
}